// round 5
// baseline (speedup 1.0000x reference)
#include <cuda_runtime.h>
#include <cuda_bf16.h>
#include <cstdint>

// Problem constants
constexpr int B  = 8;
constexpr int C  = 256;
constexpr int CQ = 128;
constexpr int N  = 4096;   // 64*64

// Scratch (device globals)
__device__ __align__(16) __nv_bfloat16 g_xb[B * C * N];            // x bf16, c-major
__device__ __align__(16) __nv_bfloat16 g_qk[B * 2 * CQ * N];       // [b][o:256][n]; o<128=q, >=128=k
__device__ __align__(16) __nv_bfloat16 g_v[B * C * N];             // [b][c][n] bf16
__device__ __align__(16) uint8_t       g_vf[B * C * N];            // v*cinv*8192, e4m3
__device__ __align__(16) uint8_t       g_Ef[(size_t)B * N * N];    // exp(S)/16, e4m3, 134 MB
__device__ float g_part[B * 32 * N];                               // per-mblock col sums
__device__ float g_cinv[B * N];
__device__ __align__(16) __nv_bfloat16 g_Wqkt[C * 2 * CQ];         // concat W^T [C][256]
__device__ __align__(16) __nv_bfloat16 g_Wvt[C * C];
__device__ float g_bqk[2 * CQ];

// ---------------------------------------------------------------------------
// helpers
// ---------------------------------------------------------------------------
__device__ __forceinline__ uint32_t su(const void* p) {
    return (uint32_t)__cvta_generic_to_shared(p);
}
__device__ __forceinline__ void ldsm_x4(uint32_t* d, uint32_t addr) {
    asm volatile("ldmatrix.sync.aligned.m8n8.x4.shared.b16 {%0,%1,%2,%3}, [%4];\n"
                 : "=r"(d[0]), "=r"(d[1]), "=r"(d[2]), "=r"(d[3]) : "r"(addr));
}
__device__ __forceinline__ void ldsm_x4_t(uint32_t* d, uint32_t addr) {
    asm volatile("ldmatrix.sync.aligned.m8n8.x4.trans.shared.b16 {%0,%1,%2,%3}, [%4];\n"
                 : "=r"(d[0]), "=r"(d[1]), "=r"(d[2]), "=r"(d[3]) : "r"(addr));
}
__device__ __forceinline__ void mma_bf16(float* c, const uint32_t* a, const uint32_t* b) {
    asm volatile(
        "mma.sync.aligned.m16n8k16.row.col.f32.bf16.bf16.f32 "
        "{%0,%1,%2,%3}, {%4,%5,%6,%7}, {%8,%9}, {%0,%1,%2,%3};\n"
        : "+f"(c[0]), "+f"(c[1]), "+f"(c[2]), "+f"(c[3])
        : "r"(a[0]), "r"(a[1]), "r"(a[2]), "r"(a[3]), "r"(b[0]), "r"(b[1]));
}
__device__ __forceinline__ void mma_e4m3(float* c, const uint32_t* a, const uint32_t* b) {
    asm volatile(
        "mma.sync.aligned.m16n8k32.row.col.f32.e4m3.e4m3.f32 "
        "{%0,%1,%2,%3}, {%4,%5,%6,%7}, {%8,%9}, {%0,%1,%2,%3};\n"
        : "+f"(c[0]), "+f"(c[1]), "+f"(c[2]), "+f"(c[3])
        : "r"(a[0]), "r"(a[1]), "r"(a[2]), "r"(a[3]), "r"(b[0]), "r"(b[1]));
}
// pack two floats to e4m3x2 (lo -> low byte)
__device__ __forceinline__ uint16_t f2_e4m3(float lo, float hi) {
    uint16_t r;
    asm volatile("cvt.rn.satfinite.e4m3x2.f32 %0, %1, %2;\n" : "=h"(r) : "f"(hi), "f"(lo));
    return r;
}
#define CP_ASYNC16(dst, src) \
    asm volatile("cp.async.cg.shared.global [%0], [%1], 16;\n" :: "r"(dst), "l"(src))
#define CP_COMMIT() asm volatile("cp.async.commit_group;\n" ::: "memory")

// scale conventions
constexpr float SE_INV = 0.0625f;          // E stored as E/16
constexpr float SV     = 8192.0f;          // V' stored as v*cinv*8192
constexpr float OUT_SCALE = 1.0f / 512.0f; // (1/16 * 8192)^-1

// ---------------------------------------------------------------------------
// small elementwise kernels
// ---------------------------------------------------------------------------
__global__ void convert_x_kernel(const float* __restrict__ x) {
    const int idx = blockIdx.x * blockDim.x + threadIdx.x;
    if (idx >= B * C * N / 2) return;
    const float2 v = reinterpret_cast<const float2*>(x)[idx];
    reinterpret_cast<__nv_bfloat162*>(g_xb)[idx] = __floats2bfloat162_rn(v.x, v.y);
}

// out[c*ldo + coff + o] = W[o*Cd + c]
__global__ void transpose_w_kernel(const float* __restrict__ W,
                                   __nv_bfloat16* __restrict__ out,
                                   int O, int Cd, int ldo, int coff) {
    const int idx = blockIdx.x * blockDim.x + threadIdx.x;
    if (idx >= O * Cd) return;
    const int c = idx / O, o = idx % O;
    out[c * ldo + coff + o] = __float2bfloat16(W[o * Cd + c]);
}

__global__ void pack_bias_kernel(const float* __restrict__ bq, const float* __restrict__ bk) {
    const int i = threadIdx.x;
    g_bqk[i] = (i < CQ) ? bq[i] : bk[i - CQ];
}

// cinv[b][n] = 1 / sum over 32 m-block partials
__global__ void reduce_part_kernel() {
    const int idx = blockIdx.x * blockDim.x + threadIdx.x;   // over B*N
    const int b = idx / N, n = idx % N;
    const float* p = g_part + (size_t)b * 32 * N + n;
    float z = 0.f;
#pragma unroll
    for (int i = 0; i < 32; i++) z += p[(size_t)i * N];
    g_cinv[idx] = 1.0f / z;
}

// g_vf[b][c][n] = e4m3( v[b][c][n] * cinv[b][n] * 8192 )
__global__ void scale_v_kernel() {
    const int idx = blockIdx.x * blockDim.x + threadIdx.x;   // over B*C*N/4
    if (idx >= B * C * N / 4) return;
    const int flat = idx * 4;
    const int b = flat / (C * N);
    const int n = flat % N;
    const float* civ = g_cinv + b * N + n;
    const __nv_bfloat162* vp = reinterpret_cast<const __nv_bfloat162*>(g_v + flat);
    const __nv_bfloat162 v0 = vp[0], v1 = vp[1];
    const uint16_t lo = f2_e4m3(__bfloat162float(v0.x) * civ[0] * SV,
                                __bfloat162float(v0.y) * civ[1] * SV);
    const uint16_t hi = f2_e4m3(__bfloat162float(v1.x) * civ[2] * SV,
                                __bfloat162float(v1.y) * civ[3] * SV);
    reinterpret_cast<uint32_t*>(g_vf)[idx] = (uint32_t)lo | ((uint32_t)hi << 16);
}

// ---------------------------------------------------------------------------
// TN GEMM (both operands k-major), cp.async 3-stage pipeline (bf16).
// Cg[i][j] = sum_k Ag[k][i] * Bg[k][j]
// EPI 0: + bias[row], bf16 store                (projections)
// EPI 1: exp(acc): e4m3 store E/16, f32 partial column sums -> g_part (QK)
// ---------------------------------------------------------------------------
constexpr int TN_STAGE = 17408;

template <int EPI>
__global__ __launch_bounds__(256) void gemm_tn_kernel(
    const __nv_bfloat16* __restrict__ Ag, const __nv_bfloat16* __restrict__ Bg,
    void* __restrict__ Cgv, const float* __restrict__ bias,
    int K, int lda, int ldb, int ldc,
    long long sA, long long sB, long long sC)
{
    extern __shared__ __align__(16) uint8_t dsm[];
    __shared__ float s_col[2][128];

    Ag += (long long)blockIdx.z * sA;
    Bg += (long long)blockIdx.z * sB;

    const int m0 = blockIdx.y * 128;
    const int n0 = blockIdx.x * 128;
    const int tid = threadIdx.x;
    const int lane = tid & 31, wid = tid >> 5;
    const int wm = wid >> 2, wn = wid & 3;
    const int mB = wm * 64, nB = wn * 32;
    const int q = lane >> 3, lr = lane & 7;

    float acc[4][4][4] = {};

    const int chunk = tid & 15, row = tid >> 4;
    const uint32_t sbase = su(dsm);
    const int Kt = K >> 5;

    for (int kt = 0; kt < Kt + 2; kt++) {
        if (kt < Kt) {
            const uint32_t sb = sbase + (kt % 3) * TN_STAGE;
            const __nv_bfloat16* As = Ag + (size_t)(kt * 32 + row) * lda + m0 + chunk * 8;
            const __nv_bfloat16* Bs = Bg + (size_t)(kt * 32 + row) * ldb + n0 + chunk * 8;
            CP_ASYNC16(sb + row * 272 + chunk * 16, As);
            CP_ASYNC16(sb + (row + 16) * 272 + chunk * 16, As + (size_t)16 * lda);
            CP_ASYNC16(sb + 8704 + row * 272 + chunk * 16, Bs);
            CP_ASYNC16(sb + 8704 + (row + 16) * 272 + chunk * 16, Bs + (size_t)16 * ldb);
            CP_COMMIT();
        }
        if (kt >= 2) {
            if (kt < Kt)       asm volatile("cp.async.wait_group 2;\n" ::: "memory");
            else if (kt == Kt) asm volatile("cp.async.wait_group 1;\n" ::: "memory");
            else               asm volatile("cp.async.wait_group 0;\n" ::: "memory");
            __syncthreads();
            const uint32_t sb = sbase + ((kt - 2) % 3) * TN_STAGE;
#pragma unroll
            for (int ks = 0; ks < 2; ks++) {
                const int kk = ks * 16;
                uint32_t Af[4][4], Bf[2][4];
#pragma unroll
                for (int im = 0; im < 4; im++)
                    ldsm_x4_t(Af[im], sb + (kk + ((q >> 1) << 3) + lr) * 272
                                         + (mB + im * 16 + ((q & 1) << 3)) * 2);
#pragma unroll
                for (int ib = 0; ib < 2; ib++)
                    ldsm_x4_t(Bf[ib], sb + 8704 + (kk + ((q & 1) << 3) + lr) * 272
                                         + (nB + ib * 16 + ((q >> 1) << 3)) * 2);
#pragma unroll
                for (int im = 0; im < 4; im++)
#pragma unroll
                    for (int in2 = 0; in2 < 4; in2++) {
                        uint32_t bfr[2] = { Bf[in2 >> 1][(in2 & 1) * 2],
                                            Bf[in2 >> 1][(in2 & 1) * 2 + 1] };
                        mma_bf16(acc[im][in2], Af[im], bfr);
                    }
            }
            __syncthreads();
        }
    }

    const int g = lane >> 2, tg = lane & 3;

    if (EPI == 0) {
        __nv_bfloat16* Cg = (__nv_bfloat16*)Cgv + (long long)blockIdx.z * sC;
#pragma unroll
        for (int im = 0; im < 4; im++) {
            const int gm = m0 + mB + im * 16 + g;
            const float b0 = bias[gm], b1 = bias[gm + 8];
#pragma unroll
            for (int in2 = 0; in2 < 4; in2++) {
                const int col = n0 + nB + in2 * 8 + tg * 2;
                *reinterpret_cast<__nv_bfloat162*>(Cg + (size_t)gm * ldc + col) =
                    __floats2bfloat162_rn(acc[im][in2][0] + b0, acc[im][in2][1] + b0);
                *reinterpret_cast<__nv_bfloat162*>(Cg + (size_t)(gm + 8) * ldc + col) =
                    __floats2bfloat162_rn(acc[im][in2][2] + b1, acc[im][in2][3] + b1);
            }
        }
    } else {
        uint8_t* Ef = (uint8_t*)Cgv + (long long)blockIdx.z * sC;
        float s[4][2] = {};
#pragma unroll
        for (int im = 0; im < 4; im++) {
            const int gm = m0 + mB + im * 16 + g;
#pragma unroll
            for (int in2 = 0; in2 < 4; in2++) {
                const int col = n0 + nB + in2 * 8 + tg * 2;
                const float e0 = __expf(acc[im][in2][0]);
                const float e1 = __expf(acc[im][in2][1]);
                const float e2 = __expf(acc[im][in2][2]);
                const float e3 = __expf(acc[im][in2][3]);
                *reinterpret_cast<uint16_t*>(Ef + (size_t)gm * ldc + col) =
                    f2_e4m3(e0 * SE_INV, e1 * SE_INV);
                *reinterpret_cast<uint16_t*>(Ef + (size_t)(gm + 8) * ldc + col) =
                    f2_e4m3(e2 * SE_INV, e3 * SE_INV);
                s[in2][0] += e0 + e2;
                s[in2][1] += e1 + e3;
            }
        }
#pragma unroll
        for (int in2 = 0; in2 < 4; in2++)
#pragma unroll
            for (int j = 0; j < 2; j++) {
                float v = s[in2][j];
                v += __shfl_xor_sync(0xFFFFFFFF, v, 4);
                v += __shfl_xor_sync(0xFFFFFFFF, v, 8);
                v += __shfl_xor_sync(0xFFFFFFFF, v, 16);
                s[in2][j] = v;
            }
        if (lane < 4) {
#pragma unroll
            for (int in2 = 0; in2 < 4; in2++)
#pragma unroll
                for (int j = 0; j < 2; j++)
                    s_col[wm][nB + in2 * 8 + lane * 2 + j] = s[in2][j];
        }
        __syncthreads();
        if (tid < 128) {
            const float z = s_col[0][tid] + s_col[1][tid];
            g_part[((size_t)blockIdx.z * 32 + blockIdx.y) * N + n0 + tid] = z;
        }
    }
}

// ---------------------------------------------------------------------------
// NT GEMM (AV) in e4m3: acc[c][m] = sum_n Vf[c][n] * Ef[m][n]
// out = gamma/512 * acc + x.  BM=128(c), BN=128(m), BK=64 bytes.
// cp.async 3-stage, smem row stride 80 B.
// ---------------------------------------------------------------------------
constexpr int NT_STAGE = 20480;   // 2 * 128*80

__global__ __launch_bounds__(256) void gemm_nt_f8_kernel(
    const float* __restrict__ x, const float* __restrict__ gamma,
    float* __restrict__ out)
{
    extern __shared__ __align__(16) uint8_t dsm[];

    const int b = blockIdx.z;
    const uint8_t* Vb = g_vf + (size_t)b * C * N;
    const uint8_t* Eb = g_Ef + (size_t)b * N * N;
    const float* xb = x + (size_t)b * C * N;
    float* ob = out + (size_t)b * C * N;

    const int c0 = blockIdx.y * 128;
    const int m0 = blockIdx.x * 128;
    const int tid = threadIdx.x;
    const int lane = tid & 31, wid = tid >> 5;
    const int wm = wid >> 2, wn = wid & 3;
    const int cB = wm * 64, mB = wn * 32;
    const int q = lane >> 3, lr = lane & 7;

    float acc[4][4][4] = {};

    const int chunk = tid & 3, row = tid >> 2;    // 64 rows, 4 chunks of 16 B
    const uint32_t sbase = su(dsm);
    constexpr int Kt = N / 64;   // 64 iterations

    for (int kt = 0; kt < Kt + 2; kt++) {
        if (kt < Kt) {
            const uint32_t sb = sbase + (kt % 3) * NT_STAGE;
            const uint8_t* Vs = Vb + (size_t)(c0 + row) * N + kt * 64 + chunk * 16;
            const uint8_t* Es = Eb + (size_t)(m0 + row) * N + kt * 64 + chunk * 16;
            CP_ASYNC16(sb + row * 80 + chunk * 16, Vs);
            CP_ASYNC16(sb + (row + 64) * 80 + chunk * 16, Vs + (size_t)64 * N);
            CP_ASYNC16(sb + 10240 + row * 80 + chunk * 16, Es);
            CP_ASYNC16(sb + 10240 + (row + 64) * 80 + chunk * 16, Es + (size_t)64 * N);
            CP_COMMIT();
        }
        if (kt >= 2) {
            if (kt < Kt)       asm volatile("cp.async.wait_group 2;\n" ::: "memory");
            else if (kt == Kt) asm volatile("cp.async.wait_group 1;\n" ::: "memory");
            else               asm volatile("cp.async.wait_group 0;\n" ::: "memory");
            __syncthreads();
            const uint32_t sb = sbase + ((kt - 2) % 3) * NT_STAGE;
#pragma unroll
            for (int ks = 0; ks < 2; ks++) {
                const int kk = ks * 32;           // byte offset within 64-B row
                uint32_t Af[4][4], Bf[2][4];
#pragma unroll
                for (int im = 0; im < 4; im++)
                    ldsm_x4(Af[im], sb + (cB + im * 16 + ((q & 1) << 3) + lr) * 80
                                       + kk + ((q >> 1) << 4));
#pragma unroll
                for (int ib = 0; ib < 2; ib++)
                    ldsm_x4(Bf[ib], sb + 10240 + (mB + ib * 16 + ((q >> 1) << 3) + lr) * 80
                                       + kk + ((q & 1) << 4));
#pragma unroll
                for (int im = 0; im < 4; im++)
#pragma unroll
                    for (int in2 = 0; in2 < 4; in2++) {
                        uint32_t bfr[2] = { Bf[in2 >> 1][(in2 & 1) * 2],
                                            Bf[in2 >> 1][(in2 & 1) * 2 + 1] };
                        mma_e4m3(acc[im][in2], Af[im], bfr);
                    }
            }
            __syncthreads();
        }
    }

    const float gs = gamma[0] * OUT_SCALE;
    const int g = lane >> 2, tg = lane & 3;
#pragma unroll
    for (int im = 0; im < 4; im++) {
        const int gc = c0 + cB + im * 16 + g;
#pragma unroll
        for (int in2 = 0; in2 < 4; in2++) {
            const int gm = m0 + mB + in2 * 8 + tg * 2;
            {
                const size_t idx = (size_t)gc * N + gm;
                const float2 xv = *reinterpret_cast<const float2*>(xb + idx);
                *reinterpret_cast<float2*>(ob + idx) =
                    make_float2(gs * acc[im][in2][0] + xv.x, gs * acc[im][in2][1] + xv.y);
            }
            {
                const size_t idx = (size_t)(gc + 8) * N + gm;
                const float2 xv = *reinterpret_cast<const float2*>(xb + idx);
                *reinterpret_cast<float2*>(ob + idx) =
                    make_float2(gs * acc[im][in2][2] + xv.x, gs * acc[im][in2][3] + xv.y);
            }
        }
    }
}

// ---------------------------------------------------------------------------
extern "C" void kernel_launch(void* const* d_in, const int* in_sizes, int n_in,
                              void* d_out, int out_size)
{
    const float* x     = (const float*)d_in[0];
    const float* Wq    = (const float*)d_in[1];
    const float* bq    = (const float*)d_in[2];
    const float* Wk    = (const float*)d_in[3];
    const float* bk    = (const float*)d_in[4];
    const float* Wv    = (const float*)d_in[5];
    const float* bv    = (const float*)d_in[6];
    const float* gamma = (const float*)d_in[7];
    float* out = (float*)d_out;

    __nv_bfloat16 *xb, *qkb, *vb, *wqkt, *wvt;
    uint8_t *Ef;
    float *bqk;
    cudaGetSymbolAddress((void**)&xb,   g_xb);
    cudaGetSymbolAddress((void**)&qkb,  g_qk);
    cudaGetSymbolAddress((void**)&vb,   g_v);
    cudaGetSymbolAddress((void**)&Ef,   g_Ef);
    cudaGetSymbolAddress((void**)&wqkt, g_Wqkt);
    cudaGetSymbolAddress((void**)&wvt,  g_Wvt);
    cudaGetSymbolAddress((void**)&bqk,  g_bqk);

    const int TN_SMEM = 3 * TN_STAGE;   // 52224
    const int NT_SMEM = 3 * NT_STAGE;   // 61440
    cudaFuncSetAttribute(gemm_tn_kernel<0>, cudaFuncAttributeMaxDynamicSharedMemorySize, TN_SMEM);
    cudaFuncSetAttribute(gemm_tn_kernel<1>, cudaFuncAttributeMaxDynamicSharedMemorySize, TN_SMEM);
    cudaFuncSetAttribute(gemm_nt_f8_kernel, cudaFuncAttributeMaxDynamicSharedMemorySize, NT_SMEM);

    // 1. conversions
    convert_x_kernel<<<(B * C * N / 2 + 255) / 256, 256>>>(x);
    transpose_w_kernel<<<(C * CQ + 255) / 256, 256>>>(Wq, wqkt, CQ, C, 2 * CQ, 0);
    transpose_w_kernel<<<(C * CQ + 255) / 256, 256>>>(Wk, wqkt, CQ, C, 2 * CQ, CQ);
    transpose_w_kernel<<<(C * C  + 255) / 256, 256>>>(Wv, wvt, C, C, C, 0);
    pack_bias_kernel<<<1, 256>>>(bq, bk);

    // 2. projections (TN: A = W^T [C][O], B = xb [C][N])
    gemm_tn_kernel<0><<<dim3(N / 128, 2 * CQ / 128, B), 256, TN_SMEM>>>(
        wqkt, xb, qkb, bqk, C, 2 * CQ, N, N, 0LL, (long long)C * N, (long long)2 * CQ * N);
    gemm_tn_kernel<0><<<dim3(N / 128, C / 128, B), 256, TN_SMEM>>>(
        wvt, xb, vb, bv, C, C, N, N, 0LL, (long long)C * N, (long long)C * N);

    // 3. E/16 = exp(q^T k)/16 (e4m3) + fused partial column sums
    gemm_tn_kernel<1><<<dim3(N / 128, N / 128, B), 256, TN_SMEM>>>(
        qkb, qkb + (size_t)CQ * N, Ef, nullptr, CQ, N, N, N,
        (long long)2 * CQ * N, (long long)2 * CQ * N, (long long)N * N);

    // 4. cinv = 1/colsum ; fold into V (fp8)
    reduce_part_kernel<<<B * N / 256, 256>>>();
    scale_v_kernel<<<(B * C * N / 4 + 255) / 256, 256>>>();

    // 5. out = gamma/512 * Vf Ef^T + x
    gemm_nt_f8_kernel<<<dim3(N / 128, C / 128, B), 256, NT_SMEM>>>(x, gamma, out);
}

// round 6
// speedup vs baseline: 1.0883x; 1.0883x over previous
#include <cuda_runtime.h>
#include <cuda_bf16.h>
#include <cstdint>

// Problem constants
constexpr int B  = 8;
constexpr int C  = 256;
constexpr int CQ = 128;
constexpr int N  = 4096;   // 64*64

// Scratch (device globals)
__device__ __align__(16) __nv_bfloat16 g_xb[B * C * N];            // x bf16, c-major
__device__ __align__(16) __nv_bfloat16 g_qkv[(size_t)B * 512 * N]; // rows: 0-127 q, 128-255 k, 256-511 v
__device__ __align__(16) __nv_bfloat16 g_E[(size_t)B * N * N];     // exp(S), bf16, 268 MB
__device__ float g_part[B * 32 * N];                               // per-mblock col sums
__device__ __align__(16) __nv_bfloat16 g_Wt[C * 512];              // concat W^T [C][512]
__device__ float g_bqkv[512];

// ---------------------------------------------------------------------------
// helpers
// ---------------------------------------------------------------------------
__device__ __forceinline__ uint32_t su(const void* p) {
    return (uint32_t)__cvta_generic_to_shared(p);
}
__device__ __forceinline__ void ldsm_x4(uint32_t* d, uint32_t addr) {
    asm volatile("ldmatrix.sync.aligned.m8n8.x4.shared.b16 {%0,%1,%2,%3}, [%4];\n"
                 : "=r"(d[0]), "=r"(d[1]), "=r"(d[2]), "=r"(d[3]) : "r"(addr));
}
__device__ __forceinline__ void ldsm_x4_t(uint32_t* d, uint32_t addr) {
    asm volatile("ldmatrix.sync.aligned.m8n8.x4.trans.shared.b16 {%0,%1,%2,%3}, [%4];\n"
                 : "=r"(d[0]), "=r"(d[1]), "=r"(d[2]), "=r"(d[3]) : "r"(addr));
}
__device__ __forceinline__ void mma_bf16(float* c, const uint32_t* a, const uint32_t* b) {
    asm volatile(
        "mma.sync.aligned.m16n8k16.row.col.f32.bf16.bf16.f32 "
        "{%0,%1,%2,%3}, {%4,%5,%6,%7}, {%8,%9}, {%0,%1,%2,%3};\n"
        : "+f"(c[0]), "+f"(c[1]), "+f"(c[2]), "+f"(c[3])
        : "r"(a[0]), "r"(a[1]), "r"(a[2]), "r"(a[3]), "r"(b[0]), "r"(b[1]));
}
#define CP_ASYNC16(dst, src) \
    asm volatile("cp.async.cg.shared.global [%0], [%1], 16;\n" :: "r"(dst), "l"(src))
#define CP_COMMIT() asm volatile("cp.async.commit_group;\n" ::: "memory")

// ---------------------------------------------------------------------------
// prep: x -> bf16  |  Wq/Wk/Wv -> concat transposed bf16  |  biases -> concat
// block-range partitioned grid.
// ---------------------------------------------------------------------------
constexpr int PREP_X_BLOCKS = B * C * N / 2 / 256;   // 16384
constexpr int PREP_W_BLOCKS = (C * 512) / 256;       // 512
constexpr int PREP_BLOCKS = PREP_X_BLOCKS + PREP_W_BLOCKS + 2;

__global__ void prep_kernel(const float* __restrict__ x,
                            const float* __restrict__ Wq, const float* __restrict__ Wk,
                            const float* __restrict__ Wv,
                            const float* __restrict__ bq, const float* __restrict__ bk,
                            const float* __restrict__ bv)
{
    const int bid = blockIdx.x;
    if (bid < PREP_X_BLOCKS) {
        const int idx = bid * 256 + threadIdx.x;
        const float2 v = reinterpret_cast<const float2*>(x)[idx];
        reinterpret_cast<__nv_bfloat162*>(g_xb)[idx] = __floats2bfloat162_rn(v.x, v.y);
    } else if (bid < PREP_X_BLOCKS + PREP_W_BLOCKS) {
        const int idx = (bid - PREP_X_BLOCKS) * 256 + threadIdx.x;  // 0 .. 131071
        if (idx < 32768) {                 // Wq: [CQ][C] -> cols 0..127
            const int c = idx >> 7, o = idx & 127;
            g_Wt[c * 512 + o] = __float2bfloat16(Wq[o * C + c]);
        } else if (idx < 65536) {          // Wk -> cols 128..255
            const int j = idx - 32768;
            const int c = j >> 7, o = j & 127;
            g_Wt[c * 512 + 128 + o] = __float2bfloat16(Wk[o * C + c]);
        } else {                           // Wv: [C][C] -> cols 256..511
            const int j = idx - 65536;
            const int c = j >> 8, o = j & 255;
            g_Wt[c * 512 + 256 + o] = __float2bfloat16(Wv[o * C + c]);
        }
    } else {
        const int i = (bid - PREP_X_BLOCKS - PREP_W_BLOCKS) * 256 + threadIdx.x;
        if (i < 512)
            g_bqkv[i] = (i < 128) ? bq[i] : (i < 256) ? bk[i - 128] : bv[i - 256];
    }
}

// ---------------------------------------------------------------------------
// reduce partial column sums -> cinv (smem), then scale v rows in place.
// grid (N/128, B), 256 threads.
// ---------------------------------------------------------------------------
__global__ __launch_bounds__(256) void finalize_v_kernel()
{
    __shared__ float s_cinv[128];
    const int b = blockIdx.y;
    const int n0 = blockIdx.x * 128;
    const int t = threadIdx.x;

    // phase 1: 128 cols x 32 partials; 2 threads per col, 16 partials each
    {
        const int col = t & 127, half = t >> 7;
        const float* p = g_part + ((size_t)b * 32 + half * 16) * N + n0 + col;
        float z = 0.f;
#pragma unroll
        for (int i = 0; i < 16; i++) z += p[(size_t)i * N];
        __shared__ float red[2][128];
        red[half][col] = z;
        __syncthreads();
        if (t < 128) s_cinv[t] = 1.0f / (red[0][t] + red[1][t]);
        __syncthreads();
    }

    // phase 2: v rows 256..511 of qkv, cols n0..n0+127, scale in place
    __nv_bfloat16* vb = g_qkv + (size_t)b * 512 * N + (size_t)256 * N;
    const int col32 = t & 63;        // u32 column (2 halves)
    const int rgrp = t >> 6;         // 0..3
    const float c0 = s_cinv[col32 * 2];
    const float c1 = s_cinv[col32 * 2 + 1];
#pragma unroll 4
    for (int r = rgrp; r < 256; r += 4) {
        uint32_t* p = reinterpret_cast<uint32_t*>(vb + (size_t)r * N + n0) + col32;
        const __nv_bfloat162 v = *reinterpret_cast<const __nv_bfloat162*>(p);
        *reinterpret_cast<__nv_bfloat162*>(p) =
            __floats2bfloat162_rn(__bfloat162float(v.x) * c0, __bfloat162float(v.y) * c1);
    }
}

// ---------------------------------------------------------------------------
// TN GEMM (both operands k-major), cp.async 3-stage pipeline (bf16).
// Cg[i][j] = sum_k Ag[k][i] * Bg[k][j]
// EPI 0: + bias[row], bf16 store              (merged qkv projection)
// EPI 1: exp(acc), bf16 store E, f32 partial column sums -> g_part  (QK)
// ---------------------------------------------------------------------------
constexpr int TN_STAGE = 17408;

template <int EPI>
__global__ __launch_bounds__(256) void gemm_tn_kernel(
    const __nv_bfloat16* __restrict__ Ag, const __nv_bfloat16* __restrict__ Bg,
    __nv_bfloat16* __restrict__ Cg, const float* __restrict__ bias,
    int K, int lda, int ldb, int ldc,
    long long sA, long long sB, long long sC)
{
    extern __shared__ __align__(16) uint8_t dsm[];
    __shared__ float s_col[2][128];

    Ag += (long long)blockIdx.z * sA;
    Bg += (long long)blockIdx.z * sB;
    Cg += (long long)blockIdx.z * sC;

    const int m0 = blockIdx.y * 128;
    const int n0 = blockIdx.x * 128;
    const int tid = threadIdx.x;
    const int lane = tid & 31, wid = tid >> 5;
    const int wm = wid >> 2, wn = wid & 3;
    const int mB = wm * 64, nB = wn * 32;
    const int q = lane >> 3, lr = lane & 7;

    float acc[4][4][4] = {};

    const int chunk = tid & 15, row = tid >> 4;
    const uint32_t sbase = su(dsm);
    const int Kt = K >> 5;

    for (int kt = 0; kt < Kt + 2; kt++) {
        if (kt < Kt) {
            const uint32_t sb = sbase + (kt % 3) * TN_STAGE;
            const __nv_bfloat16* As = Ag + (size_t)(kt * 32 + row) * lda + m0 + chunk * 8;
            const __nv_bfloat16* Bs = Bg + (size_t)(kt * 32 + row) * ldb + n0 + chunk * 8;
            CP_ASYNC16(sb + row * 272 + chunk * 16, As);
            CP_ASYNC16(sb + (row + 16) * 272 + chunk * 16, As + (size_t)16 * lda);
            CP_ASYNC16(sb + 8704 + row * 272 + chunk * 16, Bs);
            CP_ASYNC16(sb + 8704 + (row + 16) * 272 + chunk * 16, Bs + (size_t)16 * ldb);
            CP_COMMIT();
        }
        if (kt >= 2) {
            if (kt < Kt)       asm volatile("cp.async.wait_group 2;\n" ::: "memory");
            else if (kt == Kt) asm volatile("cp.async.wait_group 1;\n" ::: "memory");
            else               asm volatile("cp.async.wait_group 0;\n" ::: "memory");
            __syncthreads();
            const uint32_t sb = sbase + ((kt - 2) % 3) * TN_STAGE;
#pragma unroll
            for (int ks = 0; ks < 2; ks++) {
                const int kk = ks * 16;
                uint32_t Af[4][4], Bf[2][4];
#pragma unroll
                for (int im = 0; im < 4; im++)
                    ldsm_x4_t(Af[im], sb + (kk + ((q >> 1) << 3) + lr) * 272
                                         + (mB + im * 16 + ((q & 1) << 3)) * 2);
#pragma unroll
                for (int ib = 0; ib < 2; ib++)
                    ldsm_x4_t(Bf[ib], sb + 8704 + (kk + ((q & 1) << 3) + lr) * 272
                                         + (nB + ib * 16 + ((q >> 1) << 3)) * 2);
#pragma unroll
                for (int im = 0; im < 4; im++)
#pragma unroll
                    for (int in2 = 0; in2 < 4; in2++) {
                        uint32_t bfr[2] = { Bf[in2 >> 1][(in2 & 1) * 2],
                                            Bf[in2 >> 1][(in2 & 1) * 2 + 1] };
                        mma_bf16(acc[im][in2], Af[im], bfr);
                    }
            }
            __syncthreads();
        }
    }

    const int g = lane >> 2, tg = lane & 3;

    if (EPI == 0) {
#pragma unroll
        for (int im = 0; im < 4; im++) {
            const int gm = m0 + mB + im * 16 + g;
            const float b0 = bias[gm], b1 = bias[gm + 8];
#pragma unroll
            for (int in2 = 0; in2 < 4; in2++) {
                const int col = n0 + nB + in2 * 8 + tg * 2;
                *reinterpret_cast<__nv_bfloat162*>(Cg + (size_t)gm * ldc + col) =
                    __floats2bfloat162_rn(acc[im][in2][0] + b0, acc[im][in2][1] + b0);
                *reinterpret_cast<__nv_bfloat162*>(Cg + (size_t)(gm + 8) * ldc + col) =
                    __floats2bfloat162_rn(acc[im][in2][2] + b1, acc[im][in2][3] + b1);
            }
        }
    } else {
        float s[4][2] = {};
#pragma unroll
        for (int im = 0; im < 4; im++) {
            const int gm = m0 + mB + im * 16 + g;
#pragma unroll
            for (int in2 = 0; in2 < 4; in2++) {
                const int col = n0 + nB + in2 * 8 + tg * 2;
                const float e0 = __expf(acc[im][in2][0]);
                const float e1 = __expf(acc[im][in2][1]);
                const float e2 = __expf(acc[im][in2][2]);
                const float e3 = __expf(acc[im][in2][3]);
                *reinterpret_cast<__nv_bfloat162*>(Cg + (size_t)gm * ldc + col) =
                    __floats2bfloat162_rn(e0, e1);
                *reinterpret_cast<__nv_bfloat162*>(Cg + (size_t)(gm + 8) * ldc + col) =
                    __floats2bfloat162_rn(e2, e3);
                s[in2][0] += e0 + e2;
                s[in2][1] += e1 + e3;
            }
        }
#pragma unroll
        for (int in2 = 0; in2 < 4; in2++)
#pragma unroll
            for (int j = 0; j < 2; j++) {
                float v = s[in2][j];
                v += __shfl_xor_sync(0xFFFFFFFF, v, 4);
                v += __shfl_xor_sync(0xFFFFFFFF, v, 8);
                v += __shfl_xor_sync(0xFFFFFFFF, v, 16);
                s[in2][j] = v;
            }
        if (lane < 4) {
#pragma unroll
            for (int in2 = 0; in2 < 4; in2++)
#pragma unroll
                for (int j = 0; j < 2; j++)
                    s_col[wm][nB + in2 * 8 + lane * 2 + j] = s[in2][j];
        }
        __syncthreads();
        if (tid < 128) {
            const float z = s_col[0][tid] + s_col[1][tid];
            g_part[((size_t)blockIdx.z * 32 + blockIdx.y) * N + n0 + tid] = z;
        }
    }
}

// ---------------------------------------------------------------------------
// NT GEMM (AV): out[c][m] = gamma * sum_n V'[c][n] * E[m][n] + x[c][m]
// cp.async 3-stage. BM=128(c), BN=128(m), BK=32(n). Row stride 40 halves.
// ---------------------------------------------------------------------------
constexpr int NT_STAGE = 20480;   // 2 * 128*80

__global__ __launch_bounds__(256) void gemm_nt_kernel(
    const float* __restrict__ x, const float* __restrict__ gamma,
    float* __restrict__ out)
{
    extern __shared__ __align__(16) uint8_t dsm[];

    const int b = blockIdx.z;
    const __nv_bfloat16* Vb = g_qkv + (size_t)b * 512 * N + (size_t)256 * N;
    const __nv_bfloat16* Eb = g_E + (size_t)b * N * N;
    const float* xb = x + (size_t)b * C * N;
    float* ob = out + (size_t)b * C * N;

    const int c0 = blockIdx.y * 128;
    const int m0 = blockIdx.x * 128;
    const int tid = threadIdx.x;
    const int lane = tid & 31, wid = tid >> 5;
    const int wm = wid >> 2, wn = wid & 3;
    const int cB = wm * 64, mB = wn * 32;
    const int q = lane >> 3, lr = lane & 7;

    float acc[4][4][4] = {};

    const int chunk = tid & 3, row = tid >> 2;    // 64 rows, 4 chunks of 8 halves
    const uint32_t sbase = su(dsm);
    constexpr int Kt = N / 32;   // 128

    for (int kt = 0; kt < Kt + 2; kt++) {
        if (kt < Kt) {
            const uint32_t sb = sbase + (kt % 3) * NT_STAGE;
            const __nv_bfloat16* Vs = Vb + (size_t)(c0 + row) * N + kt * 32 + chunk * 8;
            const __nv_bfloat16* Es = Eb + (size_t)(m0 + row) * N + kt * 32 + chunk * 8;
            CP_ASYNC16(sb + row * 80 + chunk * 16, Vs);
            CP_ASYNC16(sb + (row + 64) * 80 + chunk * 16, Vs + (size_t)64 * N);
            CP_ASYNC16(sb + 10240 + row * 80 + chunk * 16, Es);
            CP_ASYNC16(sb + 10240 + (row + 64) * 80 + chunk * 16, Es + (size_t)64 * N);
            CP_COMMIT();
        }
        if (kt >= 2) {
            if (kt < Kt)       asm volatile("cp.async.wait_group 2;\n" ::: "memory");
            else if (kt == Kt) asm volatile("cp.async.wait_group 1;\n" ::: "memory");
            else               asm volatile("cp.async.wait_group 0;\n" ::: "memory");
            __syncthreads();
            const uint32_t sb = sbase + ((kt - 2) % 3) * NT_STAGE;
#pragma unroll
            for (int ks = 0; ks < 2; ks++) {
                const int kk = ks * 16;
                uint32_t Af[4][4], Bf[2][4];
#pragma unroll
                for (int im = 0; im < 4; im++)
                    ldsm_x4(Af[im], sb + (cB + im * 16 + ((q & 1) << 3) + lr) * 80
                                       + (kk + ((q >> 1) << 3)) * 2);
#pragma unroll
                for (int ib = 0; ib < 2; ib++)
                    ldsm_x4(Bf[ib], sb + 10240 + (mB + ib * 16 + ((q >> 1) << 3) + lr) * 80
                                       + (kk + ((q & 1) << 3)) * 2);
#pragma unroll
                for (int im = 0; im < 4; im++)
#pragma unroll
                    for (int in2 = 0; in2 < 4; in2++) {
                        uint32_t bfr[2] = { Bf[in2 >> 1][(in2 & 1) * 2],
                                            Bf[in2 >> 1][(in2 & 1) * 2 + 1] };
                        mma_bf16(acc[im][in2], Af[im], bfr);
                    }
            }
            __syncthreads();
        }
    }

    const float gam = gamma[0];
    const int g = lane >> 2, tg = lane & 3;
#pragma unroll
    for (int im = 0; im < 4; im++) {
        const int gc = c0 + cB + im * 16 + g;
#pragma unroll
        for (int in2 = 0; in2 < 4; in2++) {
            const int gm = m0 + mB + in2 * 8 + tg * 2;
            {
                const size_t idx = (size_t)gc * N + gm;
                const float2 xv = *reinterpret_cast<const float2*>(xb + idx);
                *reinterpret_cast<float2*>(ob + idx) =
                    make_float2(gam * acc[im][in2][0] + xv.x, gam * acc[im][in2][1] + xv.y);
            }
            {
                const size_t idx = (size_t)(gc + 8) * N + gm;
                const float2 xv = *reinterpret_cast<const float2*>(xb + idx);
                *reinterpret_cast<float2*>(ob + idx) =
                    make_float2(gam * acc[im][in2][2] + xv.x, gam * acc[im][in2][3] + xv.y);
            }
        }
    }
}

// ---------------------------------------------------------------------------
extern "C" void kernel_launch(void* const* d_in, const int* in_sizes, int n_in,
                              void* d_out, int out_size)
{
    const float* x     = (const float*)d_in[0];
    const float* Wq    = (const float*)d_in[1];
    const float* bq    = (const float*)d_in[2];
    const float* Wk    = (const float*)d_in[3];
    const float* bk    = (const float*)d_in[4];
    const float* Wv    = (const float*)d_in[5];
    const float* bv    = (const float*)d_in[6];
    const float* gamma = (const float*)d_in[7];
    float* out = (float*)d_out;

    __nv_bfloat16 *xb, *qkvb, *Eb, *wt;
    float *bqkv;
    cudaGetSymbolAddress((void**)&xb,   g_xb);
    cudaGetSymbolAddress((void**)&qkvb, g_qkv);
    cudaGetSymbolAddress((void**)&Eb,   g_E);
    cudaGetSymbolAddress((void**)&wt,   g_Wt);
    cudaGetSymbolAddress((void**)&bqkv, g_bqkv);

    const int TN_SMEM = 3 * TN_STAGE;   // 52224
    const int NT_SMEM = 3 * NT_STAGE;   // 61440
    cudaFuncSetAttribute(gemm_tn_kernel<0>, cudaFuncAttributeMaxDynamicSharedMemorySize, TN_SMEM);
    cudaFuncSetAttribute(gemm_tn_kernel<1>, cudaFuncAttributeMaxDynamicSharedMemorySize, TN_SMEM);
    cudaFuncSetAttribute(gemm_nt_kernel,    cudaFuncAttributeMaxDynamicSharedMemorySize, NT_SMEM);

    // 1. prep: x->bf16, concat W^T, concat bias   (one launch)
    prep_kernel<<<PREP_BLOCKS, 256>>>(x, Wq, Wk, Wv, bq, bk, bv);

    // 2. merged projection: qkv[512][N] = Wt^T xb + bias   (one launch)
    gemm_tn_kernel<0><<<dim3(N / 128, 4, B), 256, TN_SMEM>>>(
        wt, xb, qkvb, bqkv, C, 512, N, N, 0LL, (long long)C * N, (long long)512 * N);

    // 3. E = exp(q^T k), fused partial column sums
    gemm_tn_kernel<1><<<dim3(N / 128, N / 128, B), 256, TN_SMEM>>>(
        qkvb, qkvb + (size_t)CQ * N, Eb, nullptr, CQ, N, N, N,
        (long long)512 * N, (long long)512 * N, (long long)N * N);

    // 4. cinv + fold into V   (one launch)
    finalize_v_kernel<<<dim3(N / 128, B), 256>>>();

    // 5. out = gamma * V' E^T + x
    gemm_nt_kernel<<<dim3(N / 128, C / 128, B), 256, NT_SMEM>>>(x, gamma, out);
}

// round 7
// speedup vs baseline: 1.2019x; 1.1044x over previous
#include <cuda_runtime.h>
#include <cuda_bf16.h>
#include <cstdint>

// Problem constants
constexpr int B  = 8;
constexpr int C  = 256;
constexpr int CQ = 128;
constexpr int N  = 4096;   // 64*64

// Scratch (device globals)
__device__ __align__(16) __nv_bfloat16 g_xb[B * C * N];            // x bf16, c-major
__device__ __align__(16) __nv_bfloat16 g_qkv[(size_t)B * 512 * N]; // rows: 0-127 q, 128-255 k, 256-511 v
__device__ __align__(16) __nv_bfloat16 g_E[(size_t)B * N * N];     // exp(S), bf16, 268 MB
__device__ float g_part[B * 32 * N];                               // per-mblock col sums
__device__ __align__(16) __nv_bfloat16 g_Wt[C * 512];              // concat W^T [C][512]
__device__ float g_bqkv[512];

// ---------------------------------------------------------------------------
// helpers
// ---------------------------------------------------------------------------
__device__ __forceinline__ uint32_t su(const void* p) {
    return (uint32_t)__cvta_generic_to_shared(p);
}
__device__ __forceinline__ void ldsm_x4(uint32_t* d, uint32_t addr) {
    asm volatile("ldmatrix.sync.aligned.m8n8.x4.shared.b16 {%0,%1,%2,%3}, [%4];\n"
                 : "=r"(d[0]), "=r"(d[1]), "=r"(d[2]), "=r"(d[3]) : "r"(addr));
}
__device__ __forceinline__ void ldsm_x4_t(uint32_t* d, uint32_t addr) {
    asm volatile("ldmatrix.sync.aligned.m8n8.x4.trans.shared.b16 {%0,%1,%2,%3}, [%4];\n"
                 : "=r"(d[0]), "=r"(d[1]), "=r"(d[2]), "=r"(d[3]) : "r"(addr));
}
__device__ __forceinline__ void mma_bf16(float* c, const uint32_t* a, const uint32_t* b) {
    asm volatile(
        "mma.sync.aligned.m16n8k16.row.col.f32.bf16.bf16.f32 "
        "{%0,%1,%2,%3}, {%4,%5,%6,%7}, {%8,%9}, {%0,%1,%2,%3};\n"
        : "+f"(c[0]), "+f"(c[1]), "+f"(c[2]), "+f"(c[3])
        : "r"(a[0]), "r"(a[1]), "r"(a[2]), "r"(a[3]), "r"(b[0]), "r"(b[1]));
}
#define CP_ASYNC16(dst, src) \
    asm volatile("cp.async.cg.shared.global [%0], [%1], 16;\n" :: "r"(dst), "l"(src))
#define CP_COMMIT() asm volatile("cp.async.commit_group;\n" ::: "memory")

// ---------------------------------------------------------------------------
// prep: x -> bf16  |  Wq/Wk/Wv -> concat transposed bf16  |  biases -> concat
// ---------------------------------------------------------------------------
constexpr int PREP_X_BLOCKS = B * C * N / 2 / 256;   // 16384
constexpr int PREP_W_BLOCKS = (C * 512) / 256;       // 512
constexpr int PREP_BLOCKS = PREP_X_BLOCKS + PREP_W_BLOCKS + 2;

__global__ void prep_kernel(const float* __restrict__ x,
                            const float* __restrict__ Wq, const float* __restrict__ Wk,
                            const float* __restrict__ Wv,
                            const float* __restrict__ bq, const float* __restrict__ bk,
                            const float* __restrict__ bv)
{
    const int bid = blockIdx.x;
    if (bid < PREP_X_BLOCKS) {
        const int idx = bid * 256 + threadIdx.x;
        const float2 v = reinterpret_cast<const float2*>(x)[idx];
        reinterpret_cast<__nv_bfloat162*>(g_xb)[idx] = __floats2bfloat162_rn(v.x, v.y);
    } else if (bid < PREP_X_BLOCKS + PREP_W_BLOCKS) {
        const int idx = (bid - PREP_X_BLOCKS) * 256 + threadIdx.x;  // 0 .. 131071
        if (idx < 32768) {                 // Wq -> cols 0..127
            const int c = idx >> 7, o = idx & 127;
            g_Wt[c * 512 + o] = __float2bfloat16(Wq[o * C + c]);
        } else if (idx < 65536) {          // Wk -> cols 128..255
            const int j = idx - 32768;
            const int c = j >> 7, o = j & 127;
            g_Wt[c * 512 + 128 + o] = __float2bfloat16(Wk[o * C + c]);
        } else {                           // Wv -> cols 256..511
            const int j = idx - 65536;
            const int c = j >> 8, o = j & 255;
            g_Wt[c * 512 + 256 + o] = __float2bfloat16(Wv[o * C + c]);
        }
    } else {
        const int i = (bid - PREP_X_BLOCKS - PREP_W_BLOCKS) * 256 + threadIdx.x;
        if (i < 512)
            g_bqkv[i] = (i < 128) ? bq[i] : (i < 256) ? bk[i - 128] : bv[i - 256];
    }
}

// ---------------------------------------------------------------------------
// reduce partial column sums -> cinv (smem), then scale v rows in place.
// ---------------------------------------------------------------------------
__global__ __launch_bounds__(256) void finalize_v_kernel()
{
    __shared__ float s_cinv[128];
    const int b = blockIdx.y;
    const int n0 = blockIdx.x * 128;
    const int t = threadIdx.x;

    {
        const int col = t & 127, half = t >> 7;
        const float* p = g_part + ((size_t)b * 32 + half * 16) * N + n0 + col;
        float z = 0.f;
#pragma unroll
        for (int i = 0; i < 16; i++) z += p[(size_t)i * N];
        __shared__ float red[2][128];
        red[half][col] = z;
        __syncthreads();
        if (t < 128) s_cinv[t] = 1.0f / (red[0][t] + red[1][t]);
        __syncthreads();
    }

    __nv_bfloat16* vb = g_qkv + (size_t)b * 512 * N + (size_t)256 * N;
    const int col32 = t & 63;
    const int rgrp = t >> 6;
    const float c0 = s_cinv[col32 * 2];
    const float c1 = s_cinv[col32 * 2 + 1];
#pragma unroll 4
    for (int r = rgrp; r < 256; r += 4) {
        uint32_t* p = reinterpret_cast<uint32_t*>(vb + (size_t)r * N + n0) + col32;
        const __nv_bfloat162 v = *reinterpret_cast<const __nv_bfloat162*>(p);
        *reinterpret_cast<__nv_bfloat162*>(p) =
            __floats2bfloat162_rn(__bfloat162float(v.x) * c0, __bfloat162float(v.y) * c1);
    }
}

// ---------------------------------------------------------------------------
// TN GEMM (both operands k-major), cp.async 3-stage, 128 threads, warp 64x64.
// Block 128x128, warps 2(m) x 2(n).
// EPI 0: + bias[row], bf16 store              (merged qkv projection)
// EPI 1: exp(acc), bf16 store E, f32 partial column sums -> g_part  (QK)
// ---------------------------------------------------------------------------
constexpr int TN_STAGE = 17408;   // A 8704 + B 8704, row stride 272 B

template <int EPI>
__global__ __launch_bounds__(128) void gemm_tn_kernel(
    const __nv_bfloat16* __restrict__ Ag, const __nv_bfloat16* __restrict__ Bg,
    __nv_bfloat16* __restrict__ Cg, const float* __restrict__ bias,
    int K, int lda, int ldb, int ldc,
    long long sA, long long sB, long long sC)
{
    extern __shared__ __align__(16) uint8_t dsm[];
    __shared__ float s_col[2][128];

    Ag += (long long)blockIdx.z * sA;
    Bg += (long long)blockIdx.z * sB;
    Cg += (long long)blockIdx.z * sC;

    const int m0 = blockIdx.y * 128;
    const int n0 = blockIdx.x * 128;
    const int tid = threadIdx.x;
    const int lane = tid & 31, wid = tid >> 5;
    const int wm = wid >> 1, wn = wid & 1;
    const int mB = wm * 64, nB = wn * 64;
    const int q = lane >> 3, lr = lane & 7;

    float acc[4][8][4] = {};

    const int chunk = tid & 15, row = tid >> 4;   // row 0..7
    const uint32_t sbase = su(dsm);
    const int Kt = K >> 5;

    for (int kt = 0; kt < Kt + 2; kt++) {
        if (kt < Kt) {
            const uint32_t sb = sbase + (kt % 3) * TN_STAGE;
            const __nv_bfloat16* As = Ag + (size_t)(kt * 32 + row) * lda + m0 + chunk * 8;
            const __nv_bfloat16* Bs = Bg + (size_t)(kt * 32 + row) * ldb + n0 + chunk * 8;
#pragma unroll
            for (int r4 = 0; r4 < 4; r4++) {
                CP_ASYNC16(sb + (row + r4 * 8) * 272 + chunk * 16, As + (size_t)(r4 * 8) * lda);
                CP_ASYNC16(sb + 8704 + (row + r4 * 8) * 272 + chunk * 16, Bs + (size_t)(r4 * 8) * ldb);
            }
            CP_COMMIT();
        }
        if (kt >= 2) {
            if (kt < Kt)       asm volatile("cp.async.wait_group 2;\n" ::: "memory");
            else if (kt == Kt) asm volatile("cp.async.wait_group 1;\n" ::: "memory");
            else               asm volatile("cp.async.wait_group 0;\n" ::: "memory");
            __syncthreads();
            const uint32_t sb = sbase + ((kt - 2) % 3) * TN_STAGE;
#pragma unroll
            for (int ks = 0; ks < 2; ks++) {
                const int kk = ks * 16;
                uint32_t Af[4][4], Bf[4][4];
#pragma unroll
                for (int im = 0; im < 4; im++)
                    ldsm_x4_t(Af[im], sb + (kk + ((q >> 1) << 3) + lr) * 272
                                         + (mB + im * 16 + ((q & 1) << 3)) * 2);
#pragma unroll
                for (int ib = 0; ib < 4; ib++)
                    ldsm_x4_t(Bf[ib], sb + 8704 + (kk + ((q & 1) << 3) + lr) * 272
                                         + (nB + ib * 16 + ((q >> 1) << 3)) * 2);
#pragma unroll
                for (int im = 0; im < 4; im++)
#pragma unroll
                    for (int in2 = 0; in2 < 8; in2++) {
                        uint32_t bfr[2] = { Bf[in2 >> 1][(in2 & 1) * 2],
                                            Bf[in2 >> 1][(in2 & 1) * 2 + 1] };
                        mma_bf16(acc[im][in2], Af[im], bfr);
                    }
            }
            __syncthreads();
        }
    }

    const int g = lane >> 2, tg = lane & 3;

    if (EPI == 0) {
#pragma unroll
        for (int im = 0; im < 4; im++) {
            const int gm = m0 + mB + im * 16 + g;
            const float b0 = bias[gm], b1 = bias[gm + 8];
#pragma unroll
            for (int in2 = 0; in2 < 8; in2++) {
                const int col = n0 + nB + in2 * 8 + tg * 2;
                *reinterpret_cast<__nv_bfloat162*>(Cg + (size_t)gm * ldc + col) =
                    __floats2bfloat162_rn(acc[im][in2][0] + b0, acc[im][in2][1] + b0);
                *reinterpret_cast<__nv_bfloat162*>(Cg + (size_t)(gm + 8) * ldc + col) =
                    __floats2bfloat162_rn(acc[im][in2][2] + b1, acc[im][in2][3] + b1);
            }
        }
    } else {
        float s[8][2] = {};
#pragma unroll
        for (int im = 0; im < 4; im++) {
            const int gm = m0 + mB + im * 16 + g;
#pragma unroll
            for (int in2 = 0; in2 < 8; in2++) {
                const int col = n0 + nB + in2 * 8 + tg * 2;
                const float e0 = __expf(acc[im][in2][0]);
                const float e1 = __expf(acc[im][in2][1]);
                const float e2 = __expf(acc[im][in2][2]);
                const float e3 = __expf(acc[im][in2][3]);
                *reinterpret_cast<__nv_bfloat162*>(Cg + (size_t)gm * ldc + col) =
                    __floats2bfloat162_rn(e0, e1);
                *reinterpret_cast<__nv_bfloat162*>(Cg + (size_t)(gm + 8) * ldc + col) =
                    __floats2bfloat162_rn(e2, e3);
                s[in2][0] += e0 + e2;
                s[in2][1] += e1 + e3;
            }
        }
#pragma unroll
        for (int in2 = 0; in2 < 8; in2++)
#pragma unroll
            for (int j = 0; j < 2; j++) {
                float v = s[in2][j];
                v += __shfl_xor_sync(0xFFFFFFFF, v, 4);
                v += __shfl_xor_sync(0xFFFFFFFF, v, 8);
                v += __shfl_xor_sync(0xFFFFFFFF, v, 16);
                s[in2][j] = v;
            }
        if (lane < 4) {
#pragma unroll
            for (int in2 = 0; in2 < 8; in2++)
#pragma unroll
                for (int j = 0; j < 2; j++)
                    s_col[wm][nB + in2 * 8 + lane * 2 + j] = s[in2][j];
        }
        __syncthreads();
        {
            const float z = s_col[0][tid] + s_col[1][tid];
            g_part[((size_t)blockIdx.z * 32 + blockIdx.y) * N + n0 + tid] = z;
        }
    }
}

// ---------------------------------------------------------------------------
// NT GEMM (AV): out[c][m] = gamma * sum_n V'[c][n] * E[m][n] + x[c][m]
// 128 threads, warp tile 64x64, block 128x128, cp.async 3-stage, BK=32.
// ---------------------------------------------------------------------------
constexpr int NT_STAGE = 20480;   // 2 * 128*80

__global__ __launch_bounds__(128) void gemm_nt_kernel(
    const float* __restrict__ x, const float* __restrict__ gamma,
    float* __restrict__ out)
{
    extern __shared__ __align__(16) uint8_t dsm[];

    const int b = blockIdx.z;
    const __nv_bfloat16* Vb = g_qkv + (size_t)b * 512 * N + (size_t)256 * N;
    const __nv_bfloat16* Eb = g_E + (size_t)b * N * N;
    const float* xb = x + (size_t)b * C * N;
    float* ob = out + (size_t)b * C * N;

    const int c0 = blockIdx.y * 128;
    const int m0 = blockIdx.x * 128;
    const int tid = threadIdx.x;
    const int lane = tid & 31, wid = tid >> 5;
    const int wm = wid >> 1, wn = wid & 1;
    const int cB = wm * 64, mB = wn * 64;
    const int q = lane >> 3, lr = lane & 7;

    float acc[4][8][4] = {};

    const int chunk = tid & 3, row = tid >> 2;    // row 0..31
    const uint32_t sbase = su(dsm);
    constexpr int Kt = N / 32;   // 128

    for (int kt = 0; kt < Kt + 2; kt++) {
        if (kt < Kt) {
            const uint32_t sb = sbase + (kt % 3) * NT_STAGE;
            const __nv_bfloat16* Vs = Vb + (size_t)(c0 + row) * N + kt * 32 + chunk * 8;
            const __nv_bfloat16* Es = Eb + (size_t)(m0 + row) * N + kt * 32 + chunk * 8;
#pragma unroll
            for (int r4 = 0; r4 < 4; r4++) {
                CP_ASYNC16(sb + (row + r4 * 32) * 80 + chunk * 16, Vs + (size_t)(r4 * 32) * N);
                CP_ASYNC16(sb + 10240 + (row + r4 * 32) * 80 + chunk * 16, Es + (size_t)(r4 * 32) * N);
            }
            CP_COMMIT();
        }
        if (kt >= 2) {
            if (kt < Kt)       asm volatile("cp.async.wait_group 2;\n" ::: "memory");
            else if (kt == Kt) asm volatile("cp.async.wait_group 1;\n" ::: "memory");
            else               asm volatile("cp.async.wait_group 0;\n" ::: "memory");
            __syncthreads();
            const uint32_t sb = sbase + ((kt - 2) % 3) * NT_STAGE;
#pragma unroll
            for (int ks = 0; ks < 2; ks++) {
                const int kk = ks * 16;
                uint32_t Af[4][4], Bf[4][4];
#pragma unroll
                for (int im = 0; im < 4; im++)
                    ldsm_x4(Af[im], sb + (cB + im * 16 + ((q & 1) << 3) + lr) * 80
                                       + (kk + ((q >> 1) << 3)) * 2);
#pragma unroll
                for (int ib = 0; ib < 4; ib++)
                    ldsm_x4(Bf[ib], sb + 10240 + (mB + ib * 16 + ((q >> 1) << 3) + lr) * 80
                                       + (kk + ((q & 1) << 3)) * 2);
#pragma unroll
                for (int im = 0; im < 4; im++)
#pragma unroll
                    for (int in2 = 0; in2 < 8; in2++) {
                        uint32_t bfr[2] = { Bf[in2 >> 1][(in2 & 1) * 2],
                                            Bf[in2 >> 1][(in2 & 1) * 2 + 1] };
                        mma_bf16(acc[im][in2], Af[im], bfr);
                    }
            }
            __syncthreads();
        }
    }

    const float gam = gamma[0];
    const int g = lane >> 2, tg = lane & 3;
#pragma unroll
    for (int im = 0; im < 4; im++) {
        const int gc = c0 + cB + im * 16 + g;
#pragma unroll
        for (int in2 = 0; in2 < 8; in2++) {
            const int gm = m0 + mB + in2 * 8 + tg * 2;
            {
                const size_t idx = (size_t)gc * N + gm;
                const float2 xv = *reinterpret_cast<const float2*>(xb + idx);
                *reinterpret_cast<float2*>(ob + idx) =
                    make_float2(gam * acc[im][in2][0] + xv.x, gam * acc[im][in2][1] + xv.y);
            }
            {
                const size_t idx = (size_t)(gc + 8) * N + gm;
                const float2 xv = *reinterpret_cast<const float2*>(xb + idx);
                *reinterpret_cast<float2*>(ob + idx) =
                    make_float2(gam * acc[im][in2][2] + xv.x, gam * acc[im][in2][3] + xv.y);
            }
        }
    }
}

// ---------------------------------------------------------------------------
extern "C" void kernel_launch(void* const* d_in, const int* in_sizes, int n_in,
                              void* d_out, int out_size)
{
    const float* x     = (const float*)d_in[0];
    const float* Wq    = (const float*)d_in[1];
    const float* bq    = (const float*)d_in[2];
    const float* Wk    = (const float*)d_in[3];
    const float* bk    = (const float*)d_in[4];
    const float* Wv    = (const float*)d_in[5];
    const float* bv    = (const float*)d_in[6];
    const float* gamma = (const float*)d_in[7];
    float* out = (float*)d_out;

    __nv_bfloat16 *xb, *qkvb, *Eb, *wt;
    float *bqkv;
    cudaGetSymbolAddress((void**)&xb,   g_xb);
    cudaGetSymbolAddress((void**)&qkvb, g_qkv);
    cudaGetSymbolAddress((void**)&Eb,   g_E);
    cudaGetSymbolAddress((void**)&wt,   g_Wt);
    cudaGetSymbolAddress((void**)&bqkv, g_bqkv);

    const int TN_SMEM = 3 * TN_STAGE;   // 52224
    const int NT_SMEM = 3 * NT_STAGE;   // 61440
    cudaFuncSetAttribute(gemm_tn_kernel<0>, cudaFuncAttributeMaxDynamicSharedMemorySize, TN_SMEM);
    cudaFuncSetAttribute(gemm_tn_kernel<1>, cudaFuncAttributeMaxDynamicSharedMemorySize, TN_SMEM);
    cudaFuncSetAttribute(gemm_nt_kernel,    cudaFuncAttributeMaxDynamicSharedMemorySize, NT_SMEM);

    // 1. prep
    prep_kernel<<<PREP_BLOCKS, 256>>>(x, Wq, Wk, Wv, bq, bk, bv);

    // 2. merged projection: qkv[512][N] = Wt^T xb + bias
    gemm_tn_kernel<0><<<dim3(N / 128, 4, B), 128, TN_SMEM>>>(
        wt, xb, qkvb, bqkv, C, 512, N, N, 0LL, (long long)C * N, (long long)512 * N);

    // 3. E = exp(q^T k), fused partial column sums
    gemm_tn_kernel<1><<<dim3(N / 128, N / 128, B), 128, TN_SMEM>>>(
        qkvb, qkvb + (size_t)CQ * N, Eb, nullptr, CQ, N, N, N,
        (long long)512 * N, (long long)512 * N, (long long)N * N);

    // 4. cinv + fold into V
    finalize_v_kernel<<<dim3(N / 128, B), 256>>>();

    // 5. out = gamma * V' E^T + x
    gemm_nt_kernel<<<dim3(N / 128, C / 128, B), 128, NT_SMEM>>>(x, gamma, out);
}

// round 8
// speedup vs baseline: 1.2209x; 1.0158x over previous
#include <cuda_runtime.h>
#include <cuda_bf16.h>
#include <cstdint>

// Problem constants
constexpr int B  = 8;
constexpr int C  = 256;
constexpr int CQ = 128;
constexpr int N  = 4096;   // 64*64

// Scratch (device globals)
__device__ __align__(16) __nv_bfloat16 g_xb[B * C * N];            // x bf16, c-major
__device__ __align__(16) __nv_bfloat16 g_qkv[(size_t)B * 512 * N]; // rows: 0-127 q, 128-255 k, 256-511 v
__device__ __align__(16) __nv_bfloat16 g_E[(size_t)B * N * N];     // exp(S), bf16, 268 MB
__device__ float g_part[B * 32 * N];                               // per-mblock col sums
__device__ __align__(16) __nv_bfloat16 g_Wt[C * 512];              // concat W^T [C][512]
__device__ float g_bqkv[512];

// ---------------------------------------------------------------------------
// helpers
// ---------------------------------------------------------------------------
__device__ __forceinline__ uint32_t su(const void* p) {
    return (uint32_t)__cvta_generic_to_shared(p);
}
__device__ __forceinline__ void ldsm_x4(uint32_t* d, uint32_t addr) {
    asm volatile("ldmatrix.sync.aligned.m8n8.x4.shared.b16 {%0,%1,%2,%3}, [%4];\n"
                 : "=r"(d[0]), "=r"(d[1]), "=r"(d[2]), "=r"(d[3]) : "r"(addr));
}
__device__ __forceinline__ void ldsm_x4_t(uint32_t* d, uint32_t addr) {
    asm volatile("ldmatrix.sync.aligned.m8n8.x4.trans.shared.b16 {%0,%1,%2,%3}, [%4];\n"
                 : "=r"(d[0]), "=r"(d[1]), "=r"(d[2]), "=r"(d[3]) : "r"(addr));
}
__device__ __forceinline__ void mma_bf16(float* c, const uint32_t* a, const uint32_t* b) {
    asm volatile(
        "mma.sync.aligned.m16n8k16.row.col.f32.bf16.bf16.f32 "
        "{%0,%1,%2,%3}, {%4,%5,%6,%7}, {%8,%9}, {%0,%1,%2,%3};\n"
        : "+f"(c[0]), "+f"(c[1]), "+f"(c[2]), "+f"(c[3])
        : "r"(a[0]), "r"(a[1]), "r"(a[2]), "r"(a[3]), "r"(b[0]), "r"(b[1]));
}
#define CP_ASYNC16(dst, src) \
    asm volatile("cp.async.cg.shared.global [%0], [%1], 16;\n" :: "r"(dst), "l"(src))
#define CP_COMMIT() asm volatile("cp.async.commit_group;\n" ::: "memory")

// ---------------------------------------------------------------------------
// prep: x -> bf16  |  Wq/Wk/Wv -> concat transposed bf16  |  biases -> concat
// ---------------------------------------------------------------------------
constexpr int PREP_X_BLOCKS = B * C * N / 2 / 256;   // 16384
constexpr int PREP_W_BLOCKS = (C * 512) / 256;       // 512
constexpr int PREP_BLOCKS = PREP_X_BLOCKS + PREP_W_BLOCKS + 2;

__global__ void prep_kernel(const float* __restrict__ x,
                            const float* __restrict__ Wq, const float* __restrict__ Wk,
                            const float* __restrict__ Wv,
                            const float* __restrict__ bq, const float* __restrict__ bk,
                            const float* __restrict__ bv)
{
    const int bid = blockIdx.x;
    if (bid < PREP_X_BLOCKS) {
        const int idx = bid * 256 + threadIdx.x;
        const float2 v = reinterpret_cast<const float2*>(x)[idx];
        reinterpret_cast<__nv_bfloat162*>(g_xb)[idx] = __floats2bfloat162_rn(v.x, v.y);
    } else if (bid < PREP_X_BLOCKS + PREP_W_BLOCKS) {
        const int idx = (bid - PREP_X_BLOCKS) * 256 + threadIdx.x;  // 0 .. 131071
        if (idx < 32768) {                 // Wq -> cols 0..127
            const int c = idx >> 7, o = idx & 127;
            g_Wt[c * 512 + o] = __float2bfloat16(Wq[o * C + c]);
        } else if (idx < 65536) {          // Wk -> cols 128..255
            const int j = idx - 32768;
            const int c = j >> 7, o = j & 127;
            g_Wt[c * 512 + 128 + o] = __float2bfloat16(Wk[o * C + c]);
        } else {                           // Wv -> cols 256..511
            const int j = idx - 65536;
            const int c = j >> 8, o = j & 255;
            g_Wt[c * 512 + 256 + o] = __float2bfloat16(Wv[o * C + c]);
        }
    } else {
        const int i = (bid - PREP_X_BLOCKS - PREP_W_BLOCKS) * 256 + threadIdx.x;
        if (i < 512)
            g_bqkv[i] = (i < 128) ? bq[i] : (i < 256) ? bk[i - 128] : bv[i - 256];
    }
}

// ---------------------------------------------------------------------------
// reduce partial column sums -> cinv (smem), then scale 64 v rows in place.
// grid (N/128, 4 row-groups, B); cinv recomputed per row-group (cheap).
// ---------------------------------------------------------------------------
__global__ __launch_bounds__(256) void finalize_v_kernel()
{
    __shared__ float s_cinv[128];
    const int b = blockIdx.z;
    const int n0 = blockIdx.x * 128;
    const int r0 = blockIdx.y * 64;      // v row-group base
    const int t = threadIdx.x;

    {
        const int col = t & 127, half = t >> 7;
        const float* p = g_part + ((size_t)b * 32 + half * 16) * N + n0 + col;
        float z = 0.f;
#pragma unroll
        for (int i = 0; i < 16; i++) z += p[(size_t)i * N];
        __shared__ float red[2][128];
        red[half][col] = z;
        __syncthreads();
        if (t < 128) s_cinv[t] = 1.0f / (red[0][t] + red[1][t]);
        __syncthreads();
    }

    __nv_bfloat16* vb = g_qkv + (size_t)b * 512 * N + (size_t)(256 + r0) * N;
    const int col32 = t & 63;
    const int rgrp = t >> 6;
    const float c0 = s_cinv[col32 * 2];
    const float c1 = s_cinv[col32 * 2 + 1];
#pragma unroll
    for (int r = rgrp; r < 64; r += 4) {
        uint32_t* p = reinterpret_cast<uint32_t*>(vb + (size_t)r * N + n0) + col32;
        const __nv_bfloat162 v = *reinterpret_cast<const __nv_bfloat162*>(p);
        *reinterpret_cast<__nv_bfloat162*>(p) =
            __floats2bfloat162_rn(__bfloat162float(v.x) * c0, __bfloat162float(v.y) * c1);
    }
}

// ---------------------------------------------------------------------------
// TN GEMM (both operands k-major), cp.async 4-stage, ONE sync per k-chunk.
// 128 threads, block 128x128, warps 2(m) x 2(n), warp tile 64x64.
// EPI 0: + bias[row], bf16 store              (merged qkv projection)
// EPI 1: exp(acc), bf16 store E, f32 partial column sums -> g_part  (QK)
// ---------------------------------------------------------------------------
constexpr int TN_STAGE = 17408;   // A 8704 + B 8704, row stride 272 B
constexpr int TN_SMEM = 4 * TN_STAGE;   // 69632

template <int EPI>
__global__ __launch_bounds__(128) void gemm_tn_kernel(
    const __nv_bfloat16* __restrict__ Ag, const __nv_bfloat16* __restrict__ Bg,
    __nv_bfloat16* __restrict__ Cg, const float* __restrict__ bias,
    int K, int lda, int ldb, int ldc,
    long long sA, long long sB, long long sC)
{
    extern __shared__ __align__(16) uint8_t dsm[];
    __shared__ float s_col[2][128];

    Ag += (long long)blockIdx.z * sA;
    Bg += (long long)blockIdx.z * sB;
    Cg += (long long)blockIdx.z * sC;

    const int m0 = blockIdx.y * 128;
    const int n0 = blockIdx.x * 128;
    const int tid = threadIdx.x;
    const int lane = tid & 31, wid = tid >> 5;
    const int wm = wid >> 1, wn = wid & 1;
    const int mB = wm * 64, nB = wn * 64;
    const int q = lane >> 3, lr = lane & 7;

    float acc[4][8][4] = {};

    const int chunk = tid & 15, row = tid >> 4;   // row 0..7
    const uint32_t sbase = su(dsm);
    const int Kt = K >> 5;

    for (int kt = 0; kt < Kt + 2; kt++) {
        if (kt < Kt) {
            const uint32_t sb = sbase + (kt & 3) * TN_STAGE;
            const __nv_bfloat16* As = Ag + (size_t)(kt * 32 + row) * lda + m0 + chunk * 8;
            const __nv_bfloat16* Bs = Bg + (size_t)(kt * 32 + row) * ldb + n0 + chunk * 8;
#pragma unroll
            for (int r4 = 0; r4 < 4; r4++) {
                CP_ASYNC16(sb + (row + r4 * 8) * 272 + chunk * 16, As + (size_t)(r4 * 8) * lda);
                CP_ASYNC16(sb + 8704 + (row + r4 * 8) * 272 + chunk * 16, Bs + (size_t)(r4 * 8) * ldb);
            }
            CP_COMMIT();
        }
        if (kt >= 2) {
            if (kt < Kt)       asm volatile("cp.async.wait_group 2;\n" ::: "memory");
            else if (kt == Kt) asm volatile("cp.async.wait_group 1;\n" ::: "memory");
            else               asm volatile("cp.async.wait_group 0;\n" ::: "memory");
            __syncthreads();   // single barrier: data ready + bounds warp skew <= 1
            const uint32_t sb = sbase + ((kt - 2) & 3) * TN_STAGE;
#pragma unroll
            for (int ks = 0; ks < 2; ks++) {
                const int kk = ks * 16;
                uint32_t Af[4][4], Bf[4][4];
#pragma unroll
                for (int im = 0; im < 4; im++)
                    ldsm_x4_t(Af[im], sb + (kk + ((q >> 1) << 3) + lr) * 272
                                         + (mB + im * 16 + ((q & 1) << 3)) * 2);
#pragma unroll
                for (int ib = 0; ib < 4; ib++)
                    ldsm_x4_t(Bf[ib], sb + 8704 + (kk + ((q & 1) << 3) + lr) * 272
                                         + (nB + ib * 16 + ((q >> 1) << 3)) * 2);
#pragma unroll
                for (int im = 0; im < 4; im++)
#pragma unroll
                    for (int in2 = 0; in2 < 8; in2++) {
                        uint32_t bfr[2] = { Bf[in2 >> 1][(in2 & 1) * 2],
                                            Bf[in2 >> 1][(in2 & 1) * 2 + 1] };
                        mma_bf16(acc[im][in2], Af[im], bfr);
                    }
            }
        }
    }

    const int g = lane >> 2, tg = lane & 3;

    if (EPI == 0) {
#pragma unroll
        for (int im = 0; im < 4; im++) {
            const int gm = m0 + mB + im * 16 + g;
            const float b0 = bias[gm], b1 = bias[gm + 8];
#pragma unroll
            for (int in2 = 0; in2 < 8; in2++) {
                const int col = n0 + nB + in2 * 8 + tg * 2;
                *reinterpret_cast<__nv_bfloat162*>(Cg + (size_t)gm * ldc + col) =
                    __floats2bfloat162_rn(acc[im][in2][0] + b0, acc[im][in2][1] + b0);
                *reinterpret_cast<__nv_bfloat162*>(Cg + (size_t)(gm + 8) * ldc + col) =
                    __floats2bfloat162_rn(acc[im][in2][2] + b1, acc[im][in2][3] + b1);
            }
        }
    } else {
        float s[8][2] = {};
#pragma unroll
        for (int im = 0; im < 4; im++) {
            const int gm = m0 + mB + im * 16 + g;
#pragma unroll
            for (int in2 = 0; in2 < 8; in2++) {
                const int col = n0 + nB + in2 * 8 + tg * 2;
                const float e0 = __expf(acc[im][in2][0]);
                const float e1 = __expf(acc[im][in2][1]);
                const float e2 = __expf(acc[im][in2][2]);
                const float e3 = __expf(acc[im][in2][3]);
                *reinterpret_cast<__nv_bfloat162*>(Cg + (size_t)gm * ldc + col) =
                    __floats2bfloat162_rn(e0, e1);
                *reinterpret_cast<__nv_bfloat162*>(Cg + (size_t)(gm + 8) * ldc + col) =
                    __floats2bfloat162_rn(e2, e3);
                s[in2][0] += e0 + e2;
                s[in2][1] += e1 + e3;
            }
        }
#pragma unroll
        for (int in2 = 0; in2 < 8; in2++)
#pragma unroll
            for (int j = 0; j < 2; j++) {
                float v = s[in2][j];
                v += __shfl_xor_sync(0xFFFFFFFF, v, 4);
                v += __shfl_xor_sync(0xFFFFFFFF, v, 8);
                v += __shfl_xor_sync(0xFFFFFFFF, v, 16);
                s[in2][j] = v;
            }
        if (lane < 4) {
#pragma unroll
            for (int in2 = 0; in2 < 8; in2++)
#pragma unroll
                for (int j = 0; j < 2; j++)
                    s_col[wm][nB + in2 * 8 + lane * 2 + j] = s[in2][j];
        }
        __syncthreads();
        {
            const float z = s_col[0][tid] + s_col[1][tid];
            g_part[((size_t)blockIdx.z * 32 + blockIdx.y) * N + n0 + tid] = z;
        }
    }
}

// ---------------------------------------------------------------------------
// NT GEMM (AV): out[c][m] = gamma * sum_n V'[c][n] * E[m][n] + x[c][m]
// 128 threads, warp tile 64x64, block 128x128, cp.async 4-stage, one sync/chunk.
// ---------------------------------------------------------------------------
constexpr int NT_STAGE = 20480;   // 2 * 128*80
constexpr int NT_SMEM = 4 * NT_STAGE;   // 81920

__global__ __launch_bounds__(128) void gemm_nt_kernel(
    const float* __restrict__ x, const float* __restrict__ gamma,
    float* __restrict__ out)
{
    extern __shared__ __align__(16) uint8_t dsm[];

    const int b = blockIdx.z;
    const __nv_bfloat16* Vb = g_qkv + (size_t)b * 512 * N + (size_t)256 * N;
    const __nv_bfloat16* Eb = g_E + (size_t)b * N * N;
    const float* xb = x + (size_t)b * C * N;
    float* ob = out + (size_t)b * C * N;

    const int c0 = blockIdx.y * 128;
    const int m0 = blockIdx.x * 128;
    const int tid = threadIdx.x;
    const int lane = tid & 31, wid = tid >> 5;
    const int wm = wid >> 1, wn = wid & 1;
    const int cB = wm * 64, mB = wn * 64;
    const int q = lane >> 3, lr = lane & 7;

    float acc[4][8][4] = {};

    const int chunk = tid & 3, row = tid >> 2;    // row 0..31
    const uint32_t sbase = su(dsm);
    constexpr int Kt = N / 32;   // 128

    for (int kt = 0; kt < Kt + 2; kt++) {
        if (kt < Kt) {
            const uint32_t sb = sbase + (kt & 3) * NT_STAGE;
            const __nv_bfloat16* Vs = Vb + (size_t)(c0 + row) * N + kt * 32 + chunk * 8;
            const __nv_bfloat16* Es = Eb + (size_t)(m0 + row) * N + kt * 32 + chunk * 8;
#pragma unroll
            for (int r4 = 0; r4 < 4; r4++) {
                CP_ASYNC16(sb + (row + r4 * 32) * 80 + chunk * 16, Vs + (size_t)(r4 * 32) * N);
                CP_ASYNC16(sb + 10240 + (row + r4 * 32) * 80 + chunk * 16, Es + (size_t)(r4 * 32) * N);
            }
            CP_COMMIT();
        }
        if (kt >= 2) {
            if (kt < Kt)       asm volatile("cp.async.wait_group 2;\n" ::: "memory");
            else if (kt == Kt) asm volatile("cp.async.wait_group 1;\n" ::: "memory");
            else               asm volatile("cp.async.wait_group 0;\n" ::: "memory");
            __syncthreads();   // single barrier per chunk
            const uint32_t sb = sbase + ((kt - 2) & 3) * NT_STAGE;
#pragma unroll
            for (int ks = 0; ks < 2; ks++) {
                const int kk = ks * 16;
                uint32_t Af[4][4], Bf[4][4];
#pragma unroll
                for (int im = 0; im < 4; im++)
                    ldsm_x4(Af[im], sb + (cB + im * 16 + ((q & 1) << 3) + lr) * 80
                                       + (kk + ((q >> 1) << 3)) * 2);
#pragma unroll
                for (int ib = 0; ib < 4; ib++)
                    ldsm_x4(Bf[ib], sb + 10240 + (mB + ib * 16 + ((q >> 1) << 3) + lr) * 80
                                       + (kk + ((q & 1) << 3)) * 2);
#pragma unroll
                for (int im = 0; im < 4; im++)
#pragma unroll
                    for (int in2 = 0; in2 < 8; in2++) {
                        uint32_t bfr[2] = { Bf[in2 >> 1][(in2 & 1) * 2],
                                            Bf[in2 >> 1][(in2 & 1) * 2 + 1] };
                        mma_bf16(acc[im][in2], Af[im], bfr);
                    }
            }
        }
    }

    const float gam = gamma[0];
    const int g = lane >> 2, tg = lane & 3;
#pragma unroll
    for (int im = 0; im < 4; im++) {
        const int gc = c0 + cB + im * 16 + g;
#pragma unroll
        for (int in2 = 0; in2 < 8; in2++) {
            const int gm = m0 + mB + in2 * 8 + tg * 2;
            {
                const size_t idx = (size_t)gc * N + gm;
                const float2 xv = *reinterpret_cast<const float2*>(xb + idx);
                *reinterpret_cast<float2*>(ob + idx) =
                    make_float2(gam * acc[im][in2][0] + xv.x, gam * acc[im][in2][1] + xv.y);
            }
            {
                const size_t idx = (size_t)(gc + 8) * N + gm;
                const float2 xv = *reinterpret_cast<const float2*>(xb + idx);
                *reinterpret_cast<float2*>(ob + idx) =
                    make_float2(gam * acc[im][in2][2] + xv.x, gam * acc[im][in2][3] + xv.y);
            }
        }
    }
}

// ---------------------------------------------------------------------------
extern "C" void kernel_launch(void* const* d_in, const int* in_sizes, int n_in,
                              void* d_out, int out_size)
{
    const float* x     = (const float*)d_in[0];
    const float* Wq    = (const float*)d_in[1];
    const float* bq    = (const float*)d_in[2];
    const float* Wk    = (const float*)d_in[3];
    const float* bk    = (const float*)d_in[4];
    const float* Wv    = (const float*)d_in[5];
    const float* bv    = (const float*)d_in[6];
    const float* gamma = (const float*)d_in[7];
    float* out = (float*)d_out;

    __nv_bfloat16 *xb, *qkvb, *Eb, *wt;
    float *bqkv;
    cudaGetSymbolAddress((void**)&xb,   g_xb);
    cudaGetSymbolAddress((void**)&qkvb, g_qkv);
    cudaGetSymbolAddress((void**)&Eb,   g_E);
    cudaGetSymbolAddress((void**)&wt,   g_Wt);
    cudaGetSymbolAddress((void**)&bqkv, g_bqkv);

    cudaFuncSetAttribute(gemm_tn_kernel<0>, cudaFuncAttributeMaxDynamicSharedMemorySize, TN_SMEM);
    cudaFuncSetAttribute(gemm_tn_kernel<1>, cudaFuncAttributeMaxDynamicSharedMemorySize, TN_SMEM);
    cudaFuncSetAttribute(gemm_nt_kernel,    cudaFuncAttributeMaxDynamicSharedMemorySize, NT_SMEM);

    // 1. prep
    prep_kernel<<<PREP_BLOCKS, 256>>>(x, Wq, Wk, Wv, bq, bk, bv);

    // 2. merged projection: qkv[512][N] = Wt^T xb + bias
    gemm_tn_kernel<0><<<dim3(N / 128, 4, B), 128, TN_SMEM>>>(
        wt, xb, qkvb, bqkv, C, 512, N, N, 0LL, (long long)C * N, (long long)512 * N);

    // 3. E = exp(q^T k), fused partial column sums
    gemm_tn_kernel<1><<<dim3(N / 128, N / 128, B), 128, TN_SMEM>>>(
        qkvb, qkvb + (size_t)CQ * N, Eb, nullptr, CQ, N, N, N,
        (long long)512 * N, (long long)512 * N, (long long)N * N);

    // 4. cinv + fold into V  (4 row-groups per n-slab)
    finalize_v_kernel<<<dim3(N / 128, 4, B), 256>>>();

    // 5. out = gamma * V' E^T + x
    gemm_nt_kernel<<<dim3(N / 128, C / 128, B), 128, NT_SMEM>>>(x, gamma, out);
}